// round 2
// baseline (speedup 1.0000x reference)
#include <cuda_runtime.h>
#include <cstdint>

// C4ByteNibbleVM — integer semantics of the one-hot "neural VM":
//   s = a + b (u32, little-endian ripple carry), out_byte[i] = s_byte[i] ^ a_byte[i],
// emitted as exact one-hot [B,4,256] f32 (reference softmax output is one-hot
// to ~1e-7, far inside the 1e-3 threshold).
//
// R1 -> R2 change: two-stage early-exit read. Each 256-float row's 1.0 is
// uniform-random; read the first half (128 floats = one float4/lane), and only
// read the second half if the warp-uniform ballot says the hit wasn't there.
// Expected input read: 75% of 512MB -> total traffic ~640MB instead of 768MB.

__global__ __launch_bounds__(256) void c4_vm_kernel(
    const float* __restrict__ a,
    const float* __restrict__ b,
    float* __restrict__ out,
    int nwords)
{
    const int warp = (blockIdx.x * (blockDim.x >> 5)) + (threadIdx.x >> 5);
    const int lane = threadIdx.x & 31;
    if (warp >= nwords) return;

    const float4* __restrict__ a4 = reinterpret_cast<const float4*>(a) + (size_t)warp * 256;
    const float4* __restrict__ b4 = reinterpret_cast<const float4*>(b) + (size_t)warp * 256;

    // ---- Stage 1: first half of all 8 rows (4 a-rows, 4 b-rows), MLP=8 ----
    float4 h0[8];
#pragma unroll
    for (int i = 0; i < 4; i++) {
        h0[i]     = __ldcs(&a4[i * 64 + lane]);
        h0[4 + i] = __ldcs(&b4[i * 64 + lane]);
    }

    unsigned ball[8];
    unsigned idx[8];
#pragma unroll
    for (int r = 0; r < 8; r++) {
        const float4 v = h0[r];
        const bool p = (v.x > 0.5f) | (v.y > 0.5f) | (v.z > 0.5f) | (v.w > 0.5f);
        ball[r] = __ballot_sync(0xffffffffu, p);
        unsigned loc = 0;
        if (v.x > 0.5f) loc = lane * 4 + 0;
        if (v.y > 0.5f) loc = lane * 4 + 1;
        if (v.z > 0.5f) loc = lane * 4 + 2;
        if (v.w > 0.5f) loc = lane * 4 + 3;
        idx[r] = __reduce_add_sync(0xffffffffu, loc);   // index within half (valid iff ball[r]!=0)
    }

    // ---- Stage 2: predicated second-half loads for unresolved rows, batched ----
    float4 h1[8];
    const float4 fz = make_float4(0.f, 0.f, 0.f, 0.f);
#pragma unroll
    for (int i = 0; i < 4; i++) {
        h1[i]     = (ball[i]     == 0) ? __ldcs(&a4[i * 64 + 32 + lane]) : fz;
        h1[4 + i] = (ball[4 + i] == 0) ? __ldcs(&b4[i * 64 + 32 + lane]) : fz;
    }

#pragma unroll
    for (int r = 0; r < 8; r++) {
        if (ball[r] == 0) {                              // warp-uniform branch
            const float4 v = h1[r];
            unsigned loc = 0;
            if (v.x > 0.5f) loc = lane * 4 + 0;
            if (v.y > 0.5f) loc = lane * 4 + 1;
            if (v.z > 0.5f) loc = lane * 4 + 2;
            if (v.w > 0.5f) loc = lane * 4 + 3;
            idx[r] = 128 + __reduce_add_sync(0xffffffffu, loc);
        }
    }

    // ---- Integer VM op ----
    const unsigned av = idx[0] | (idx[1] << 8) | (idx[2] << 16) | (idx[3] << 24);
    const unsigned bv = idx[4] | (idx[5] << 8) | (idx[6] << 16) | (idx[7] << 24);
    const unsigned o  = (av + bv) ^ av;

    // ---- One-hot output: 4 rows x 1KB, fully coalesced 128-bit stores ----
    float4* __restrict__ o4 = reinterpret_cast<float4*>(out) + (size_t)warp * 256;

#pragma unroll
    for (int i = 0; i < 4; i++) {
        const unsigned ob = (o >> (8 * i)) & 0xffu;
        const int q = ob >> 2;                           // which float4 (0..63)
        const int e = ob & 3;                            // element within float4
        float4 z0 = make_float4(0.f, 0.f, 0.f, 0.f);
        float4 z1 = make_float4(0.f, 0.f, 0.f, 0.f);
        if (q == lane)      (&z0.x)[e] = 1.0f;
        if (q == lane + 32) (&z1.x)[e] = 1.0f;
        o4[i * 64 + lane]      = z0;
        o4[i * 64 + 32 + lane] = z1;
    }
}

extern "C" void kernel_launch(void* const* d_in, const int* in_sizes, int n_in,
                              void* d_out, int out_size)
{
    const float* a = (const float*)d_in[0];   // a_bytes [B,4,256]
    const float* b = (const float*)d_in[1];   // b_bytes [B,4,256]
    float* out = (float*)d_out;               // [B,4,256]

    const int nwords = in_sizes[0] / 1024;    // B
    const int warps_per_block = 8;            // 256 threads
    const int blocks = (nwords + warps_per_block - 1) / warps_per_block;

    c4_vm_kernel<<<blocks, 256>>>(a, b, out, nwords);
}

// round 3
// speedup vs baseline: 1.4540x; 1.4540x over previous
#include <cuda_runtime.h>
#include <cstdint>

// C4ByteNibbleVM — integer semantics of the one-hot "neural VM":
//   s = a + b (u32, little-endian ripple carry), out_byte[i] = s_byte[i] ^ a_byte[i],
// output as exact one-hot [B,4,256] f32 (reference softmax is one-hot to ~1e-7).
//
// R2 -> R3: keep the two-stage early-exit read (expected input = 75% of 512MB)
// but fix the R2 regression:
//   * stage-2 loads overwrite the SAME h[8] registers (predicated @P LDG, no
//     second array, no zero-select) -> ~50 regs instead of 71
//   * stage-2 decode is unconditional on all rows + final select (no BSSY/BSYNC)
//   * __launch_bounds__(256,5) pins occupancy at 40 warps/SM (R1 level)

__global__ __launch_bounds__(256, 5) void c4_vm_kernel(
    const float* __restrict__ a,
    const float* __restrict__ b,
    float* __restrict__ out,
    int nwords)
{
    const int warp = (blockIdx.x * (blockDim.x >> 5)) + (threadIdx.x >> 5);
    const int lane = threadIdx.x & 31;
    if (warp >= nwords) return;

    const float4* __restrict__ a4 = reinterpret_cast<const float4*>(a) + (size_t)warp * 256;
    const float4* __restrict__ b4 = reinterpret_cast<const float4*>(b) + (size_t)warp * 256;

    // ---- Stage 1: first half of all 8 rows (4 a-rows, 4 b-rows), MLP=8 ----
    float4 h[8];
#pragma unroll
    for (int i = 0; i < 4; i++) {
        h[i]     = __ldcs(&a4[i * 64 + lane]);
        h[4 + i] = __ldcs(&b4[i * 64 + lane]);
    }

    unsigned idx1[8];
    unsigned unres = 0;                         // bit r set -> row r not found in first half
#pragma unroll
    for (int r = 0; r < 8; r++) {
        const float4 v = h[r];
        unsigned loc = 0;
        bool p = false;
        if (v.x > 0.5f) { loc = lane * 4 + 0; p = true; }
        if (v.y > 0.5f) { loc = lane * 4 + 1; p = true; }
        if (v.z > 0.5f) { loc = lane * 4 + 2; p = true; }
        if (v.w > 0.5f) { loc = lane * 4 + 3; p = true; }
        const unsigned bal = __ballot_sync(0xffffffffu, p);
        idx1[r] = __reduce_add_sync(0xffffffffu, loc);
        if (bal == 0) unres |= (1u << r);
    }

    // ---- Stage 2: predicated reload of unresolved rows into the SAME regs ----
#pragma unroll
    for (int i = 0; i < 4; i++) {
        if (unres & (1u << i))       h[i]     = __ldcs(&a4[i * 64 + 32 + lane]);
        if (unres & (1u << (4 + i))) h[4 + i] = __ldcs(&b4[i * 64 + 32 + lane]);
    }

    // Unconditional decode of all rows (stale rows decode garbage), then select.
    unsigned idx[8];
#pragma unroll
    for (int r = 0; r < 8; r++) {
        const float4 v = h[r];
        unsigned loc = 0;
        if (v.x > 0.5f) loc = lane * 4 + 0;
        if (v.y > 0.5f) loc = lane * 4 + 1;
        if (v.z > 0.5f) loc = lane * 4 + 2;
        if (v.w > 0.5f) loc = lane * 4 + 3;
        const unsigned idx2 = 128 + __reduce_add_sync(0xffffffffu, loc);
        idx[r] = (unres & (1u << r)) ? idx2 : idx1[r];
    }

    // ---- Integer VM op ----
    const unsigned av = idx[0] | (idx[1] << 8) | (idx[2] << 16) | (idx[3] << 24);
    const unsigned bv = idx[4] | (idx[5] << 8) | (idx[6] << 16) | (idx[7] << 24);
    const unsigned o  = (av + bv) ^ av;

    // ---- One-hot output: 4 rows x 1KB, coalesced 128-bit stores ----
    float4* __restrict__ o4 = reinterpret_cast<float4*>(out) + (size_t)warp * 256;

#pragma unroll
    for (int i = 0; i < 4; i++) {
        const unsigned ob = (o >> (8 * i)) & 0xffu;
        const int q = ob >> 2;                  // which float4 (0..63)
        const int e = ob & 3;                   // element within float4
        float4 z0 = make_float4(0.f, 0.f, 0.f, 0.f);
        float4 z1 = make_float4(0.f, 0.f, 0.f, 0.f);
        if (q == lane)      (&z0.x)[e] = 1.0f;
        if (q == lane + 32) (&z1.x)[e] = 1.0f;
        o4[i * 64 + lane]      = z0;
        o4[i * 64 + 32 + lane] = z1;
    }
}

extern "C" void kernel_launch(void* const* d_in, const int* in_sizes, int n_in,
                              void* d_out, int out_size)
{
    const float* a = (const float*)d_in[0];   // a_bytes [B,4,256]
    const float* b = (const float*)d_in[1];   // b_bytes [B,4,256]
    float* out = (float*)d_out;               // [B,4,256]

    const int nwords = in_sizes[0] / 1024;    // B
    const int warps_per_block = 8;            // 256 threads
    const int blocks = (nwords + warps_per_block - 1) / warps_per_block;

    c4_vm_kernel<<<blocks, 256>>>(a, b, out, nwords);
}

// round 4
// speedup vs baseline: 1.5473x; 1.0642x over previous
#include <cuda_runtime.h>
#include <cstdint>

// C4ByteNibbleVM — integer semantics of the one-hot "neural VM":
//   s = a + b (u32, little-endian ripple carry), out_byte[i] = s_byte[i] ^ a_byte[i],
// output as exact one-hot [B,4,256] f32 (reference softmax is one-hot to ~1e-7).
//
// R3 -> R4: 4-stage early-exit probing at 256B granularity (float2 per lane).
// Expected input read per 1024B row: 256*(1+2+3+4)/4 = 640B (vs 768B for the
// 2-stage 512B scheme). Decode per row-stage = 2 ballots + FLO (no REDUX).
// Register-lean (~40) so __launch_bounds__(256,6) gives 48 warps/SM to hide
// the extra dependent epochs.

__global__ __launch_bounds__(256, 6) void c4_vm_kernel(
    const float* __restrict__ a,
    const float* __restrict__ b,
    float* __restrict__ out,
    int nwords)
{
    const int warp = (blockIdx.x * (blockDim.x >> 5)) + (threadIdx.x >> 5);
    const int lane = threadIdx.x & 31;
    if (warp >= nwords) return;

    // Row = 256 floats = 128 float2. Word block = 4 rows = 512 float2.
    const float2* __restrict__ pa =
        reinterpret_cast<const float2*>(a) + (size_t)warp * 512 + lane;
    const float2* __restrict__ pb =
        reinterpret_cast<const float2*>(b) + (size_t)warp * 512 + lane;

    unsigned pos[8];
    unsigned unres = 0xffu;                     // bit r: row r not yet located

#pragma unroll
    for (int s = 0; s < 4; s++) {               // stage s covers floats [s*64, s*64+64)
        if (unres) {                            // warp-uniform
            float2 v[8];
#pragma unroll
            for (int r = 0; r < 8; r++) {
                if (unres & (1u << r)) {        // warp-uniform, predicated load
                    const float2* p = (r < 4) ? pa : pb;
                    v[r] = __ldcs(p + (r & 3) * 128 + s * 32);
                }
            }
#pragma unroll
            for (int r = 0; r < 8; r++) {
                if (unres & (1u << r)) {        // warp-uniform
                    const unsigned bx = __ballot_sync(0xffffffffu, v[r].x > 0.5f);
                    const unsigned by = __ballot_sync(0xffffffffu, v[r].y > 0.5f);
                    const unsigned cb = bx | by;
                    if (cb) {                   // warp-uniform
                        pos[r] = s * 64 + ((__ffs(cb) - 1) << 1) + (bx ? 0u : 1u);
                        unres &= ~(1u << r);
                    }
                }
            }
        }
    }

    // ---- Integer VM op ----
    const unsigned av = pos[0] | (pos[1] << 8) | (pos[2] << 16) | (pos[3] << 24);
    const unsigned bv = pos[4] | (pos[5] << 8) | (pos[6] << 16) | (pos[7] << 24);
    const unsigned o  = (av + bv) ^ av;

    // ---- One-hot output: 4 rows x 1KB, coalesced 128-bit stores ----
    float4* __restrict__ o4 = reinterpret_cast<float4*>(out) + (size_t)warp * 256;

#pragma unroll
    for (int i = 0; i < 4; i++) {
        const unsigned ob = (o >> (8 * i)) & 0xffu;
        const int q = ob >> 2;                  // which float4 (0..63)
        const int e = ob & 3;                   // element within float4
        float4 z0 = make_float4(0.f, 0.f, 0.f, 0.f);
        float4 z1 = make_float4(0.f, 0.f, 0.f, 0.f);
        if (q == lane)      (&z0.x)[e] = 1.0f;
        if (q == lane + 32) (&z1.x)[e] = 1.0f;
        o4[i * 64 + lane]      = z0;
        o4[i * 64 + 32 + lane] = z1;
    }
}

extern "C" void kernel_launch(void* const* d_in, const int* in_sizes, int n_in,
                              void* d_out, int out_size)
{
    const float* a = (const float*)d_in[0];   // a_bytes [B,4,256]
    const float* b = (const float*)d_in[1];   // b_bytes [B,4,256]
    float* out = (float*)d_out;               // [B,4,256]

    const int nwords = in_sizes[0] / 1024;    // B
    const int warps_per_block = 8;            // 256 threads
    const int blocks = (nwords + warps_per_block - 1) / warps_per_block;

    c4_vm_kernel<<<blocks, 256>>>(a, b, out, nwords);
}